// round 15
// baseline (speedup 1.0000x reference)
#include <cuda_runtime.h>
#include <cuda_fp16.h>
#include <cstdint>

#define NN   50000
#define EE   1600000
#define INC  128
#define OUTC 64
#define BKT  96          // fixed bucket capacity per node (mean deg 32, +11 sigma)

// Scratch (allocation-free contract: __device__ globals)
__device__ int   g_cnt[NN];                         // degree / fill cursor
__device__ __align__(16) __half g_feat[(size_t)(NN + 1) * OUTC];  // +1 zero row
__device__ int   g_src[(size_t)NN * BKT];           // bucketed BYTE offsets (row<<7)
__device__ int   g_is64;

// ---------------- zero + dtype detect (fused) ----------------
__global__ void zero_k(const int* __restrict__ ei32, int n) {
    int i = blockIdx.x * blockDim.x + threadIdx.x;
    if (i < n) g_cnt[i] = 0;
    if (blockIdx.x == 0) {
        // dtype probe: odd 32-bit words are zero iff int64 (high halves)
        __shared__ int zeros;
        if (threadIdx.x == 0) zeros = 0;
        __syncthreads();
        int z = (ei32[2 * threadIdx.x + 1] == 0) ? 1 : 0;
        atomicAdd(&zeros, z);
        __syncthreads();
        if (threadIdx.x == 0) g_is64 = (zeros > 128) ? 1 : 0;
    }
    if (blockIdx.x == 1 && threadIdx.x < 32) {
        // zero-feature pad row (index NN): 64 halves = 32 uint32
        ((unsigned int*)(g_feat + (size_t)NN * OUTC))[threadIdx.x] = 0u;
    }
}

__device__ __forceinline__ int load_idx(const int* ei32, size_t pos) {
    if (g_is64) return (int)((const long long*)ei32)[pos];
    return ei32[pos];
}

// ---------------- bucketed fill: one pass, 4 edges/thread -----------------
// Stores BYTE offsets (row * 128) so the gather skips the IMAD.WIDE.
__global__ void fill_k(const int* __restrict__ ei32, int E) {
    int e0 = (blockIdx.x * blockDim.x + threadIdx.x) * 4;
    if (e0 >= E) return;
    if (e0 + 4 <= E) {
        int r[4], c[4];
        if (g_is64) {
            const longlong2* pr = (const longlong2*)ei32;
            const longlong2* pc = (const longlong2*)((const long long*)ei32 + E);
            longlong2 rv0 = pr[(e0 >> 1) + 0], rv1 = pr[(e0 >> 1) + 1];
            longlong2 cv0 = pc[(e0 >> 1) + 0], cv1 = pc[(e0 >> 1) + 1];
            r[0] = (int)rv0.x; r[1] = (int)rv0.y; r[2] = (int)rv1.x; r[3] = (int)rv1.y;
            c[0] = (int)cv0.x; c[1] = (int)cv0.y; c[2] = (int)cv1.x; c[3] = (int)cv1.y;
        } else {
            int4 rv = ((const int4*)ei32)[e0 >> 2];
            int4 cv = ((const int4*)(ei32 + E))[e0 >> 2];
            r[0] = rv.x; r[1] = rv.y; r[2] = rv.z; r[3] = rv.w;
            c[0] = cv.x; c[1] = cv.y; c[2] = cv.z; c[3] = cv.w;
        }
        int p[4];
#pragma unroll
        for (int j = 0; j < 4; j++) p[j] = atomicAdd(&g_cnt[c[j]], 1);
#pragma unroll
        for (int j = 0; j < 4; j++) g_src[(size_t)c[j] * BKT + p[j]] = r[j] << 7;
    } else {
        for (int e = e0; e < E; e++) {
            int rr = load_idx(ei32, (size_t)e);
            int cc = load_idx(ei32, (size_t)E + e);
            int p = atomicAdd(&g_cnt[cc], 1);
            g_src[(size_t)cc * BKT + p] = rr << 7;
        }
    }
}

// ---------------- linear (UNSCALED): g_feat = fp16(x@W) --------------------
// No g_cnt dependence -> runs concurrently with zero_k/fill_k on stream s2.
__global__ __launch_bounds__(128) void gemm_k(
    const float* __restrict__ x, const float* __restrict__ W, int n)
{
    __shared__ __align__(16) float Ws[INC * OUTC];   // [k][o], 32 KB
    const float4* W4 = (const float4*)W;
    float4* Ws4 = (float4*)Ws;
    for (int i = threadIdx.x; i < INC * (OUTC / 4); i += 128) Ws4[i] = W4[i];
    __syncthreads();

    int row = blockIdx.x * 128 + threadIdx.x;
    if (row >= n) return;

    unsigned long long acc2[OUTC / 2];   // packed f32x2 accumulators
#pragma unroll
    for (int o = 0; o < OUTC / 2; o++) acc2[o] = 0ULL;

    const float4* xr = (const float4*)(x + (size_t)row * INC);
    const ulonglong2* WsP = (const ulonglong2*)Ws;  // [k][o4] as 2 packed pairs
#pragma unroll 4
    for (int k4 = 0; k4 < INC / 4; k4++) {
        float4 xq = __ldg(xr + k4);
        float xv[4] = {xq.x, xq.y, xq.z, xq.w};
#pragma unroll
        for (int j = 0; j < 4; j++) {
            int k = k4 * 4 + j;
            unsigned long long xx;
            asm("mov.b64 %0, {%1, %1};" : "=l"(xx) : "r"(__float_as_uint(xv[j])));
#pragma unroll
            for (int o4 = 0; o4 < OUTC / 4; o4++) {
                ulonglong2 wv = WsP[k * (OUTC / 4) + o4];
                asm("fma.rn.f32x2 %0, %1, %2, %0;" : "+l"(acc2[o4 * 2 + 0]) : "l"(xx), "l"(wv.x));
                asm("fma.rn.f32x2 %0, %1, %2, %0;" : "+l"(acc2[o4 * 2 + 1]) : "l"(xx), "l"(wv.y));
            }
        }
    }

    __half2* gp = (__half2*)(g_feat + (size_t)row * OUTC);  // 32 half2
#pragma unroll
    for (int o2 = 0; o2 < OUTC / 2; o2++) {
        unsigned int lo, hi;
        asm("mov.b64 {%0, %1}, %2;" : "=r"(lo), "=r"(hi) : "l"(acc2[o2]));
        gp[o2] = __floats2half2_rn(__uint_as_float(lo), __uint_as_float(hi));
    }
}

// ---------------- post-join scale: feat[i] *= dinv[i], vectorized ---------
// One thread per 16 bytes (4 half2); 8 threads per feature row.
__global__ __launch_bounds__(256) void scale_k(int n) {
    int t = blockIdx.x * blockDim.x + threadIdx.x;   // over n*8 uint4
    if (t >= n * 8) return;
    int row = t >> 3;
    float s = rsqrtf((float)(g_cnt[row] + 1));       // +1 self-loop
    __half2 sh = __float2half2_rn(s);
    uint4* p = (uint4*)g_feat + t;
    uint4 v = *p;
    __half2* h = (__half2*)&v;
    h[0] = __hmul2(h[0], sh);
    h[1] = __hmul2(h[1], sh);
    h[2] = __hmul2(h[2], sh);
    h[3] = __hmul2(h[3], sh);
    *p = v;
}

// ---------------- warp-per-node gather + epilogue ----------------
// g_src holds BYTE offsets; per edge: SHFL + IADD + LDG.32 + HADD2.
// Pads hit the L1-resident zero row. 16 NAMED half2 accumulators ->
// 16 independent LDG->HADD2 chains per warp (covers L2-hit latency).
__global__ __launch_bounds__(256) void gather_k(
    const float* __restrict__ b, float* __restrict__ out, int n)
{
    int warp = (blockIdx.x * blockDim.x + threadIdx.x) >> 5;
    if (warp >= n) return;
    int lane = threadIdx.x & 31;

    const __half2* gf = (const __half2*)g_feat;   // 32 half2 per node
    float2 self = __half22float2(gf[(size_t)warp * 32 + lane]);  // self-loop

    const char* gbase = (const char*)g_feat + lane * 4;

    __half2 z = __float2half2_rn(0.f);
    __half2 a0 = z, a1 = z, a2 = z, a3 = z, a4 = z, a5 = z, a6 = z, a7 = z;
    __half2 c0 = z, c1 = z, c2 = z, c3 = z, c4 = z, c5 = z, c6 = z, c7 = z;

    int cnt = g_cnt[warp];
    const int* bucket = g_src + (size_t)warp * BKT;

#define GSTEP(K, ACC) { int _o = __shfl_sync(0xffffffffu, off, (K)); \
                        ACC = __hadd2(ACC, __ldg((const __half2*)(gbase + _o))); }

    for (int base = 0; base < cnt; base += 32) {
        int rem = cnt - base;
        int off = (lane < rem) ? bucket[base + lane] : (NN << 7);  // pad
        GSTEP(0, a0) GSTEP(1, a1) GSTEP(2, a2) GSTEP(3, a3)
        GSTEP(4, a4) GSTEP(5, a5) GSTEP(6, a6) GSTEP(7, a7)
        if (rem > 8) {
            GSTEP(8,  c0) GSTEP(9,  c1) GSTEP(10, c2) GSTEP(11, c3)
            GSTEP(12, c4) GSTEP(13, c5) GSTEP(14, c6) GSTEP(15, c7)
        }
        if (rem > 16) {
            GSTEP(16, a0) GSTEP(17, a1) GSTEP(18, a2) GSTEP(19, a3)
            GSTEP(20, a4) GSTEP(21, a5) GSTEP(22, a6) GSTEP(23, a7)
        }
        if (rem > 24) {
            GSTEP(24, c0) GSTEP(25, c1) GSTEP(26, c2) GSTEP(27, c3)
            GSTEP(28, c4) GSTEP(29, c5) GSTEP(30, c6) GSTEP(31, c7)
        }
    }
#undef GSTEP

    // combine in fp32
    float2 acc = self;
    {
        float2 v;
        v = __half22float2(a0); acc.x += v.x; acc.y += v.y;
        v = __half22float2(a1); acc.x += v.x; acc.y += v.y;
        v = __half22float2(a2); acc.x += v.x; acc.y += v.y;
        v = __half22float2(a3); acc.x += v.x; acc.y += v.y;
        v = __half22float2(a4); acc.x += v.x; acc.y += v.y;
        v = __half22float2(a5); acc.x += v.x; acc.y += v.y;
        v = __half22float2(a6); acc.x += v.x; acc.y += v.y;
        v = __half22float2(a7); acc.x += v.x; acc.y += v.y;
        v = __half22float2(c0); acc.x += v.x; acc.y += v.y;
        v = __half22float2(c1); acc.x += v.x; acc.y += v.y;
        v = __half22float2(c2); acc.x += v.x; acc.y += v.y;
        v = __half22float2(c3); acc.x += v.x; acc.y += v.y;
        v = __half22float2(c4); acc.x += v.x; acc.y += v.y;
        v = __half22float2(c5); acc.x += v.x; acc.y += v.y;
        v = __half22float2(c6); acc.x += v.x; acc.y += v.y;
        v = __half22float2(c7); acc.x += v.x; acc.y += v.y;
    }

    float  s  = rsqrtf((float)(cnt + 1));
    float2 bq = __ldg((const float2*)b + lane);
    float2 o;
    o.x = acc.x * s + bq.x;
    o.y = acc.y * s + bq.y;
    ((float2*)out)[(size_t)warp * 32 + lane] = o;
}

extern "C" void kernel_launch(void* const* d_in, const int* in_sizes, int n_in,
                              void* d_out, int out_size)
{
    const float* x    = (const float*)d_in[0];
    const int*   ei32 = (const int*)d_in[1];
    const float* W    = (const float*)d_in[2];
    const float* b    = (const float*)d_in[3];
    float* out = (float*)d_out;

    int n = in_sizes[0] / INC;   // 50000
    int E = in_sizes[1] / 2;     // 1600000

    // Fork: gemm (no deps on edge phase) runs on s2 concurrently with
    // zero+fill on the capture (default) stream. NonBlocking required.
    // Created per call; intentionally not destroyed (capture-legal).
    cudaStream_t s2;
    cudaEvent_t ev_start, ev_gemm;
    cudaStreamCreateWithFlags(&s2, cudaStreamNonBlocking);
    cudaEventCreateWithFlags(&ev_start, cudaEventDisableTiming);
    cudaEventCreateWithFlags(&ev_gemm, cudaEventDisableTiming);

    cudaEventRecord(ev_start, 0);
    cudaStreamWaitEvent(s2, ev_start, 0);
    gemm_k<<<(n + 127) / 128, 128, 0, s2>>>(x, W, n);   // unscaled h
    cudaEventRecord(ev_gemm, s2);

    zero_k<<<(n + 255) / 256, 256>>>(ei32, n);          // + dtype + zero row
    fill_k<<<(E / 4 + 255) / 256, 256>>>(ei32, E);      // byte-offset buckets

    cudaStreamWaitEvent(0, ev_gemm, 0);                 // join
    scale_k<<<(n * 8 + 255) / 256, 256>>>(n);           // feat *= dinv (vec)
    gather_k<<<(n * 32 + 255) / 256, 256>>>(b, out, n); // 16-chain gather
}

// round 16
// speedup vs baseline: 1.0647x; 1.0647x over previous
#include <cuda_runtime.h>
#include <cuda_fp16.h>
#include <cstdint>

#define NN   50000
#define EE   1600000
#define INC  128
#define OUTC 64
#define BKT  96          // fixed bucket capacity per node (mean deg 32, +11 sigma)

// Scratch (allocation-free contract: __device__ globals)
__device__ int   g_cnt[NN];                         // degree / fill cursor
__device__ __align__(16) __half g_feat[(size_t)(NN + 1) * OUTC];  // +1 zero row
__device__ int   g_src[(size_t)NN * BKT];           // bucketed BYTE offsets (row<<7)
__device__ int   g_is64;

// ---------------- zero + dtype detect (fused) ----------------
__global__ void zero_k(const int* __restrict__ ei32, int n) {
    int i = blockIdx.x * blockDim.x + threadIdx.x;
    if (i < n) g_cnt[i] = 0;
    if (blockIdx.x == 0) {
        // dtype probe: odd 32-bit words are zero iff int64 (high halves)
        __shared__ int zeros;
        if (threadIdx.x == 0) zeros = 0;
        __syncthreads();
        int z = (ei32[2 * threadIdx.x + 1] == 0) ? 1 : 0;
        atomicAdd(&zeros, z);
        __syncthreads();
        if (threadIdx.x == 0) g_is64 = (zeros > 128) ? 1 : 0;
    }
    if (blockIdx.x == 1 && threadIdx.x < 32) {
        // zero-feature pad row (index NN): 64 halves = 32 uint32
        ((unsigned int*)(g_feat + (size_t)NN * OUTC))[threadIdx.x] = 0u;
    }
}

__device__ __forceinline__ int load_idx(const int* ei32, size_t pos) {
    if (g_is64) return (int)((const long long*)ei32)[pos];
    return ei32[pos];
}

// ---------------- bucketed fill: one pass, 4 edges/thread -----------------
// Stores BYTE offsets (row * 128) so the gather skips the IMAD.WIDE.
__global__ void fill_k(const int* __restrict__ ei32, int E) {
    int e0 = (blockIdx.x * blockDim.x + threadIdx.x) * 4;
    if (e0 >= E) return;
    if (e0 + 4 <= E) {
        int r[4], c[4];
        if (g_is64) {
            const longlong2* pr = (const longlong2*)ei32;
            const longlong2* pc = (const longlong2*)((const long long*)ei32 + E);
            longlong2 rv0 = pr[(e0 >> 1) + 0], rv1 = pr[(e0 >> 1) + 1];
            longlong2 cv0 = pc[(e0 >> 1) + 0], cv1 = pc[(e0 >> 1) + 1];
            r[0] = (int)rv0.x; r[1] = (int)rv0.y; r[2] = (int)rv1.x; r[3] = (int)rv1.y;
            c[0] = (int)cv0.x; c[1] = (int)cv0.y; c[2] = (int)cv1.x; c[3] = (int)cv1.y;
        } else {
            int4 rv = ((const int4*)ei32)[e0 >> 2];
            int4 cv = ((const int4*)(ei32 + E))[e0 >> 2];
            r[0] = rv.x; r[1] = rv.y; r[2] = rv.z; r[3] = rv.w;
            c[0] = cv.x; c[1] = cv.y; c[2] = cv.z; c[3] = cv.w;
        }
        int p[4];
#pragma unroll
        for (int j = 0; j < 4; j++) p[j] = atomicAdd(&g_cnt[c[j]], 1);
#pragma unroll
        for (int j = 0; j < 4; j++) g_src[(size_t)c[j] * BKT + p[j]] = r[j] << 7;
    } else {
        for (int e = e0; e < E; e++) {
            int rr = load_idx(ei32, (size_t)e);
            int cc = load_idx(ei32, (size_t)E + e);
            int p = atomicAdd(&g_cnt[cc], 1);
            g_src[(size_t)cc * BKT + p] = rr << 7;
        }
    }
}

// ---------------- linear (UNSCALED): g_feat = fp16(x@W) --------------------
// No g_cnt dependence -> runs concurrently with zero_k/fill_k on stream s2.
__global__ __launch_bounds__(128) void gemm_k(
    const float* __restrict__ x, const float* __restrict__ W, int n)
{
    __shared__ __align__(16) float Ws[INC * OUTC];   // [k][o], 32 KB
    const float4* W4 = (const float4*)W;
    float4* Ws4 = (float4*)Ws;
    for (int i = threadIdx.x; i < INC * (OUTC / 4); i += 128) Ws4[i] = W4[i];
    __syncthreads();

    int row = blockIdx.x * 128 + threadIdx.x;
    if (row >= n) return;

    unsigned long long acc2[OUTC / 2];   // packed f32x2 accumulators
#pragma unroll
    for (int o = 0; o < OUTC / 2; o++) acc2[o] = 0ULL;

    const float4* xr = (const float4*)(x + (size_t)row * INC);
    const ulonglong2* WsP = (const ulonglong2*)Ws;  // [k][o4] as 2 packed pairs
#pragma unroll 4
    for (int k4 = 0; k4 < INC / 4; k4++) {
        float4 xq = __ldg(xr + k4);
        float xv[4] = {xq.x, xq.y, xq.z, xq.w};
#pragma unroll
        for (int j = 0; j < 4; j++) {
            int k = k4 * 4 + j;
            unsigned long long xx;
            asm("mov.b64 %0, {%1, %1};" : "=l"(xx) : "r"(__float_as_uint(xv[j])));
#pragma unroll
            for (int o4 = 0; o4 < OUTC / 4; o4++) {
                ulonglong2 wv = WsP[k * (OUTC / 4) + o4];
                asm("fma.rn.f32x2 %0, %1, %2, %0;" : "+l"(acc2[o4 * 2 + 0]) : "l"(xx), "l"(wv.x));
                asm("fma.rn.f32x2 %0, %1, %2, %0;" : "+l"(acc2[o4 * 2 + 1]) : "l"(xx), "l"(wv.y));
            }
        }
    }

    __half2* gp = (__half2*)(g_feat + (size_t)row * OUTC);  // 32 half2
#pragma unroll
    for (int o2 = 0; o2 < OUTC / 2; o2++) {
        unsigned int lo, hi;
        asm("mov.b64 {%0, %1}, %2;" : "=r"(lo), "=r"(hi) : "l"(acc2[o2]));
        gp[o2] = __floats2half2_rn(__uint_as_float(lo), __uint_as_float(hi));
    }
}

// ---------------- post-join scale: feat[i] *= dinv[i], vectorized ---------
// One thread per 16 bytes (4 half2); 8 threads per feature row.
__global__ __launch_bounds__(256) void scale_k(int n) {
    int t = blockIdx.x * blockDim.x + threadIdx.x;   // over n*8 uint4
    if (t >= n * 8) return;
    int row = t >> 3;
    float s = rsqrtf((float)(g_cnt[row] + 1));       // +1 self-loop
    __half2 sh = __float2half2_rn(s);
    uint4* p = (uint4*)g_feat + t;
    uint4 v = *p;
    __half2* h = (__half2*)&v;
    h[0] = __hmul2(h[0], sh);
    h[1] = __hmul2(h[1], sh);
    h[2] = __hmul2(h[2], sh);
    h[3] = __hmul2(h[3], sh);
    *p = v;
}

// ---------------- warp-per-node gather + epilogue ----------------
// g_src holds BYTE offsets; per edge: SHFL + IADD + LDG.32 + HADD2.
// Pads hit the L1-resident zero row. 8 NAMED half2 accumulators
// (measured-best configuration, R13).
__global__ __launch_bounds__(256) void gather_k(
    const float* __restrict__ b, float* __restrict__ out, int n)
{
    int warp = (blockIdx.x * blockDim.x + threadIdx.x) >> 5;
    if (warp >= n) return;
    int lane = threadIdx.x & 31;

    const __half2* gf = (const __half2*)g_feat;   // 32 half2 per node
    float2 self = __half22float2(gf[(size_t)warp * 32 + lane]);  // self-loop

    const char* gbase = (const char*)g_feat + lane * 4;

    __half2 z = __float2half2_rn(0.f);
    __half2 a0 = z, a1 = z, a2 = z, a3 = z, a4 = z, a5 = z, a6 = z, a7 = z;

    int cnt = g_cnt[warp];
    const int* bucket = g_src + (size_t)warp * BKT;

#define GSTEP(K, ACC) { int _o = __shfl_sync(0xffffffffu, off, (K)); \
                        ACC = __hadd2(ACC, __ldg((const __half2*)(gbase + _o))); }

    for (int base = 0; base < cnt; base += 32) {
        int rem = cnt - base;
        int off = (lane < rem) ? bucket[base + lane] : (NN << 7);  // pad
        GSTEP(0, a0) GSTEP(1, a1) GSTEP(2, a2) GSTEP(3, a3)
        GSTEP(4, a4) GSTEP(5, a5) GSTEP(6, a6) GSTEP(7, a7)
        if (rem > 8) {
            GSTEP(8,  a0) GSTEP(9,  a1) GSTEP(10, a2) GSTEP(11, a3)
            GSTEP(12, a4) GSTEP(13, a5) GSTEP(14, a6) GSTEP(15, a7)
        }
        if (rem > 16) {
            GSTEP(16, a0) GSTEP(17, a1) GSTEP(18, a2) GSTEP(19, a3)
            GSTEP(20, a4) GSTEP(21, a5) GSTEP(22, a6) GSTEP(23, a7)
        }
        if (rem > 24) {
            GSTEP(24, a0) GSTEP(25, a1) GSTEP(26, a2) GSTEP(27, a3)
            GSTEP(28, a4) GSTEP(29, a5) GSTEP(30, a6) GSTEP(31, a7)
        }
    }
#undef GSTEP

    // combine in fp32
    float2 acc = self;
    {
        float2 v;
        v = __half22float2(a0); acc.x += v.x; acc.y += v.y;
        v = __half22float2(a1); acc.x += v.x; acc.y += v.y;
        v = __half22float2(a2); acc.x += v.x; acc.y += v.y;
        v = __half22float2(a3); acc.x += v.x; acc.y += v.y;
        v = __half22float2(a4); acc.x += v.x; acc.y += v.y;
        v = __half22float2(a5); acc.x += v.x; acc.y += v.y;
        v = __half22float2(a6); acc.x += v.x; acc.y += v.y;
        v = __half22float2(a7); acc.x += v.x; acc.y += v.y;
    }

    float  s  = rsqrtf((float)(cnt + 1));
    float2 bq = __ldg((const float2*)b + lane);
    float2 o;
    o.x = acc.x * s + bq.x;
    o.y = acc.y * s + bq.y;
    ((float2*)out)[(size_t)warp * 32 + lane] = o;
}

extern "C" void kernel_launch(void* const* d_in, const int* in_sizes, int n_in,
                              void* d_out, int out_size)
{
    const float* x    = (const float*)d_in[0];
    const int*   ei32 = (const int*)d_in[1];
    const float* W    = (const float*)d_in[2];
    const float* b    = (const float*)d_in[3];
    float* out = (float*)d_out;

    int n = in_sizes[0] / INC;   // 50000
    int E = in_sizes[1] / 2;     // 1600000

    // Fork: gemm (no deps on edge phase) runs on s2 concurrently with
    // zero+fill on the capture (default) stream. NonBlocking required.
    // Created per call; intentionally not destroyed (capture-legal).
    cudaStream_t s2;
    cudaEvent_t ev_start, ev_gemm;
    cudaStreamCreateWithFlags(&s2, cudaStreamNonBlocking);
    cudaEventCreateWithFlags(&ev_start, cudaEventDisableTiming);
    cudaEventCreateWithFlags(&ev_gemm, cudaEventDisableTiming);

    cudaEventRecord(ev_start, 0);
    cudaStreamWaitEvent(s2, ev_start, 0);
    gemm_k<<<(n + 127) / 128, 128, 0, s2>>>(x, W, n);   // unscaled h
    cudaEventRecord(ev_gemm, s2);

    zero_k<<<(n + 255) / 256, 256>>>(ei32, n);          // + dtype + zero row
    fill_k<<<(E / 4 + 255) / 256, 256>>>(ei32, E);      // byte-offset buckets

    cudaStreamWaitEvent(0, ev_gemm, 0);                 // join
    scale_k<<<(n * 8 + 255) / 256, 256>>>(n);           // feat *= dinv (vec)
    gather_k<<<(n * 32 + 255) / 256, 256>>>(b, out, n); // 8-acc gather
}